// round 14
// baseline (speedup 1.0000x reference)
#include <cuda_runtime.h>

#define FEATURES   2048
#define F4         (FEATURES / 4)     // 512 float4 per row
#define SCALE      4.0f
#define TPB        512
#define UNROLL     8
#define PER_BLOCK  (TPB * UNROLL)     // 4096 float4 = 8 rows

// out = sigmoid(SCALE * (x * w[f] + b[f])) over [32768, 2048] fp32. HBM-bound.
//
// Layout trick: TPB == F4 and per-thread stride == F4, so the feature index
// is tid for EVERY unrolled element -> one register-resident (w,b) pair per
// thread, zero per-element index math.
// Sigmoid via MUFU.TANH: sigmoid(4t) = 0.5 + 0.5*tanh(2t), with the 2 folded
// into w/b once. Per element: FFMA + TANH + FFMA.
// 8 front-batched independent LDG.128 (MLP=8); x/out streamed .cs.

__device__ __forceinline__ float tanh_approx(float z) {
    float t;
    asm("tanh.approx.f32 %0, %1;" : "=f"(t) : "f"(z));
    return t;
}

__global__ void __launch_bounds__(TPB) onetoone_sigmoid_tanh(
    const float4* __restrict__ x,
    const float4* __restrict__ w,
    const float4* __restrict__ b,
    float4* __restrict__ out)
{
    const int tid  = threadIdx.x;                 // 0..511 == feature vec4 index
    const int base = blockIdx.x * PER_BLOCK + tid;

    // One (w,b) pair per thread; fold SCALE/2 = 2.0 in once.
    float4 wv = __ldg(&w[tid]);
    float4 bv = __ldg(&b[tid]);
    wv.x *= 2.0f; wv.y *= 2.0f; wv.z *= 2.0f; wv.w *= 2.0f;
    bv.x *= 2.0f; bv.y *= 2.0f; bv.z *= 2.0f; bv.w *= 2.0f;

    // Front-batched independent loads (MLP_p1 = 8).
    float4 xv[UNROLL];
    #pragma unroll
    for (int u = 0; u < UNROLL; u++)
        xv[u] = __ldcs(&x[base + u * F4]);

    #pragma unroll
    for (int u = 0; u < UNROLL; u++) {
        float4 r;
        r.x = fmaf(tanh_approx(fmaf(xv[u].x, wv.x, bv.x)), 0.5f, 0.5f);
        r.y = fmaf(tanh_approx(fmaf(xv[u].y, wv.y, bv.y)), 0.5f, 0.5f);
        r.z = fmaf(tanh_approx(fmaf(xv[u].z, wv.z, bv.z)), 0.5f, 0.5f);
        r.w = fmaf(tanh_approx(fmaf(xv[u].w, wv.w, bv.w)), 0.5f, 0.5f);
        __stcs(&out[base + u * F4], r);
    }
}

// Generic guarded fallback (only used if sizes ever change).
__global__ void __launch_bounds__(256) onetoone_sigmoid_generic(
    const float4* __restrict__ x,
    const float4* __restrict__ w,
    const float4* __restrict__ b,
    float4* __restrict__ out,
    int total4)
{
    int i = blockIdx.x * blockDim.x + threadIdx.x;
    if (i >= total4) return;
    int fi = i & (F4 - 1);
    float4 xv = __ldcs(&x[i]);
    float4 wv = __ldg(&w[fi]);
    float4 bv = __ldg(&b[fi]);
    float4 r;
    r.x = fmaf(tanh_approx(2.0f * fmaf(xv.x, wv.x, bv.x)), 0.5f, 0.5f);
    r.y = fmaf(tanh_approx(2.0f * fmaf(xv.y, wv.y, bv.y)), 0.5f, 0.5f);
    r.z = fmaf(tanh_approx(2.0f * fmaf(xv.z, wv.z, bv.z)), 0.5f, 0.5f);
    r.w = fmaf(tanh_approx(2.0f * fmaf(xv.w, wv.w, bv.w)), 0.5f, 0.5f);
    __stcs(&out[i], r);
}

extern "C" void kernel_launch(void* const* d_in, const int* in_sizes, int n_in,
                              void* d_out, int out_size)
{
    const float4* x = (const float4*)d_in[0];   // input  [N, FEATURES] fp32
    const float4* w = (const float4*)d_in[1];   // weight [FEATURES]    fp32
    const float4* b = (const float4*)d_in[2];   // bias   [FEATURES]    fp32
    float4* out = (float4*)d_out;

    int total4 = out_size / 4;                  // 16,777,216
    if ((total4 % PER_BLOCK) == 0) {
        int blocks = total4 / PER_BLOCK;        // 4096
        onetoone_sigmoid_tanh<<<blocks, TPB>>>(x, w, b, out);
    } else {
        int blocks = (total4 + 255) / 256;
        onetoone_sigmoid_generic<<<blocks, 256>>>(x, w, b, out, total4);
    }
}